// round 3
// baseline (speedup 1.0000x reference)
#include <cuda_runtime.h>
#include <cuda_bf16.h>
#include <cstdint>

// ---------------------------------------------------------------------------
// SimpleHOGModule: 3D gradient HOG binning.
//   input  x: (64,64,64) f32
//   output  : (1, 8, 8, 78, 78, 78) f32   (78 = 64 + 2*8 - 2)
//
// Central-difference gradients (the 3x3x3 "sobel" weight is a fixed stencil),
// magnitude + atan2/acos angles, then <=3 one-hot bin deposits per voxel.
// Each thread owns a pair of voxels (w, w+1) and writes their full 64-bin
// column: dense float2 zero stores, then scalar overwrites for the deposits.
// Pure store-bandwidth bound: 121.5 MB of output writes.
// ---------------------------------------------------------------------------

#define DIN   64
#define DOUT  78
#define SLICE (78*78*78)          // 474552 elements per bin slice

__device__ __forceinline__ float ldx(const float* __restrict__ x,
                                     int z, int y, int xx) {
    if ((unsigned)z < (unsigned)DIN &&
        (unsigned)y < (unsigned)DIN &&
        (unsigned)xx < (unsigned)DIN)
        return __ldg(&x[(z * DIN + y) * DIN + xx]);
    return 0.0f;
}

__device__ __forceinline__ void voxel_bins(const float* __restrict__ x,
                                           int d, int h, int w,
                                           int& b0, int& b1, int& b2,
                                           float& w0, float& w1, float& w2) {
    const float PI_F  = 3.14159265358979323846f;
    const float EPS_F = 2.2204460492503131e-16f;

    int zc = d - 7, yc = h - 7, xc = w - 7;
    float sz = ldx(x, zc + 1, yc, xc) - ldx(x, zc - 1, yc, xc);
    float sy = ldx(x, zc, yc + 1, xc) - ldx(x, zc, yc - 1, xc);
    float sx = ldx(x, zc, yc, xc + 1) - ldx(x, zc, yc, xc - 1);

    // match reference eval order: (sz^2 + sy^2) + sx^2
    float mag = sqrtf((sz * sz + sy * sy) + sx * sx);
    float theta = atan2f(sy, sx);
    float r = sz / (mag + EPS_F);
    r = fminf(1.0f, fmaxf(-1.0f, r));   // guard acos domain (ref would NaN; clamp is
                                        // a no-op whenever ref is finite)
    float phi = acosf(r);

    float t_raw = theta / PI_F * 8.0f;  // NOTE: theta scaled by phi_bins (faithful)
    float p_raw = phi   / PI_F * 8.0f;
    float t_fr = t_raw - truncf(t_raw); // torch.frac semantics
    float p_fr = p_raw - truncf(p_raw);

    int i0 = ((int)floorf(t_raw)) & 7;  // &7 == floored mod 8 (pow-2, negatives ok)
    int i1 = ((int)ceilf (t_raw)) & 7;
    int i2 = ((int)floorf(p_raw)) & 7;
    int i3 = ((int)ceilf (p_raw)) & 7;

    float f0 = fabsf(t_fr),        f1 = fabsf(1.0f - t_fr);
    float f2 = fabsf(p_fr),        f3 = fabsf(1.0f - p_fr);

    w0 = (f0 * f2) * mag;   // -> (i0, i2)  (scatter_ set)
    w1 = (f0 * f3) * mag;   // -> (i0, i3)  (scatter_add)
    w2 = (f1 * f2) * mag;   // -> (i1, i2)  (scatter_add)

    b0 = i0 * 8 + i2;
    b1 = i0 * 8 + i3;
    b2 = i1 * 8 + i2;

    // fold colliding deposits so each surviving bin gets one store
    if (b1 == b0) w0 += w1;
    if (b2 == b0) w0 += w2;
    else if (b2 == b1) w1 += w2;
}

__global__ __launch_bounds__(256)
void hog_kernel(const float* __restrict__ x, float* __restrict__ out) {
    const int NPAIR = DOUT * DOUT * (DOUT / 2);   // 237276
    int pid = blockIdx.x * blockDim.x + threadIdx.x;
    if (pid >= NPAIR) return;

    int wp = pid % (DOUT / 2);
    int t  = pid / (DOUT / 2);
    int h  = t % DOUT;
    int d  = t / DOUT;
    int w  = wp * 2;

    int   b0a, b1a, b2a, b0b, b1b, b2b;
    float w0a, w1a, w2a, w0b, w1b, w2b;
    voxel_bins(x, d, h, w,     b0a, b1a, b2a, w0a, w1a, w2a);
    voxel_bins(x, d, h, w + 1, b0b, b1b, b2b, w0b, w1b, w2b);

    float* outp = out + ((size_t)d * DOUT + h) * DOUT + w;

    // dense zero fill of this voxel-pair's 64-bin column (coalesced STG.64)
    float2 z2 = make_float2(0.0f, 0.0f);
#pragma unroll
    for (int b = 0; b < 64; b++) {
        *reinterpret_cast<float2*>(outp + (size_t)b * SLICE) = z2;
    }

    // deposits, voxel A (lane +0) — same-thread overwrite, program-ordered
    outp[(size_t)b0a * SLICE] = w0a;
    if (b1a != b0a)               outp[(size_t)b1a * SLICE] = w1a;
    if (b2a != b0a && b2a != b1a) outp[(size_t)b2a * SLICE] = w2a;

    // deposits, voxel B (lane +1)
    outp[(size_t)b0b * SLICE + 1] = w0b;
    if (b1b != b0b)               outp[(size_t)b1b * SLICE + 1] = w1b;
    if (b2b != b0b && b2b != b1b) outp[(size_t)b2b * SLICE + 1] = w2b;
}

extern "C" void kernel_launch(void* const* d_in, const int* in_sizes, int n_in,
                              void* d_out, int out_size) {
    const float* x = (const float*)d_in[0];   // (64,64,64) f32; d_in[1] (weight) unused: fixed stencil
    float* out = (float*)d_out;               // (1,8,8,78,78,78) f32

    const int NPAIR = DOUT * DOUT * (DOUT / 2);
    int threads = 256;
    int blocks = (NPAIR + threads - 1) / threads;
    hog_kernel<<<blocks, threads>>>(x, out);
}